// round 1
// baseline (speedup 1.0000x reference)
#include <cuda_runtime.h>
#include <cuda_bf16.h>
#include <math.h>

// Problem constants
#define BB   2
#define SS   1024
#define HH   4096
#define NH   32
#define NKV  8
#define HD   128
#define MROWS (BB*SS)          // 2048
#define GQA  (NH/NKV)          // 4

// -------------------- scratch (device globals; no allocation) --------------------
__device__ float g_q  [MROWS * NH  * HD];   // 2048 x 4096
__device__ float g_k  [MROWS * NKV * HD];   // 2048 x 1024
__device__ float g_v  [MROWS * NKV * HD];   // 2048 x 1024
__device__ float g_ctx[MROWS * NH  * HD];   // 2048 x 4096
__device__ float g_cos[SS * (HD/2)];        // 1024 x 64
__device__ float g_sin[SS * (HD/2)];

// -------------------- SGEMM: C[M,N] = A[M,K] * B[K,N], all row-major --------------------
// 128x128 block, BK=8, 256 threads, 8x8 per-thread microtile.
// M,N,K are multiples of 128/8 here (no bounds checks needed).
__global__ __launch_bounds__(256) void sgemm128(const float* __restrict__ A,
                                                const float* __restrict__ B,
                                                float* __restrict__ C,
                                                int M, int N, int K) {
    __shared__ float As[8][128];
    __shared__ float Bs[8][128];

    const int tid = threadIdx.x;            // 0..255
    const int tx  = tid & 15;               // 0..15
    const int ty  = tid >> 4;               // 0..15
    const int bm  = blockIdx.y * 128;
    const int bn  = blockIdx.x * 128;

    const int aRow = tid >> 1;              // 0..127
    const int aCol = (tid & 1) * 4;         // 0 or 4
    const int bRow = tid >> 5;              // 0..7
    const int bCol = (tid & 31) * 4;        // 0..124

    const float* Aptr = A + (size_t)(bm + aRow) * K + aCol;
    const float* Bptr = B + (size_t)bRow * N + bn + bCol;

    float acc[8][8];
#pragma unroll
    for (int i = 0; i < 8; ++i)
#pragma unroll
        for (int j = 0; j < 8; ++j) acc[i][j] = 0.f;

    for (int kt = 0; kt < K; kt += 8) {
        float4 av = *(const float4*)(Aptr + kt);
        float4 bv = *(const float4*)(Bptr + (size_t)kt * N);
        As[aCol + 0][aRow] = av.x;
        As[aCol + 1][aRow] = av.y;
        As[aCol + 2][aRow] = av.z;
        As[aCol + 3][aRow] = av.w;
        *(float4*)&Bs[bRow][bCol] = bv;
        __syncthreads();

#pragma unroll
        for (int kk = 0; kk < 8; ++kk) {
            float4 a0 = *(const float4*)&As[kk][ty * 8];
            float4 a1 = *(const float4*)&As[kk][ty * 8 + 4];
            float4 b0 = *(const float4*)&Bs[kk][tx * 8];
            float4 b1 = *(const float4*)&Bs[kk][tx * 8 + 4];
            float a[8] = {a0.x,a0.y,a0.z,a0.w,a1.x,a1.y,a1.z,a1.w};
            float b[8] = {b0.x,b0.y,b0.z,b0.w,b1.x,b1.y,b1.z,b1.w};
#pragma unroll
            for (int i = 0; i < 8; ++i)
#pragma unroll
                for (int j = 0; j < 8; ++j)
                    acc[i][j] += a[i] * b[j];
        }
        __syncthreads();
    }

    float* Cb = C + (size_t)(bm + ty * 8) * N + bn + tx * 8;
#pragma unroll
    for (int i = 0; i < 8; ++i) {
        float4 v0 = {acc[i][0], acc[i][1], acc[i][2], acc[i][3]};
        float4 v1 = {acc[i][4], acc[i][5], acc[i][6], acc[i][7]};
        *(float4*)(Cb + (size_t)i * N)     = v0;
        *(float4*)(Cb + (size_t)i * N + 4) = v1;
    }
}

// -------------------- RoPE cos/sin table (fp64 precompute -> fp32) --------------------
__global__ void rope_table_kernel() {
    int i = blockIdx.x * blockDim.x + threadIdx.x;      // 0..65535
    if (i >= SS * (HD/2)) return;
    int s = i >> 6;          // position
    int f = i & 63;          // frequency index
    double inv = exp(-(double)f / 64.0 * log(10000.0));
    double a   = (double)s * inv;
    g_cos[i] = (float)cos(a);
    g_sin[i] = (float)sin(a);
}

// -------------------- fused RMSNorm + RoPE (in place on Q and K) --------------------
// grid: (2048 rows, 40 heads [0..31 -> Q, 32..39 -> K]), 128 threads
__global__ __launch_bounds__(128) void norm_rope_kernel(float* __restrict__ Q,
                                                        float* __restrict__ Kb,
                                                        const float* __restrict__ qw,
                                                        const float* __restrict__ kw) {
    const int row = blockIdx.x;       // 0..2047
    const int h   = blockIdx.y;       // 0..39
    const int d   = threadIdx.x;      // 0..127

    float* ptr;
    const float* w;
    if (h < NH) { ptr = Q  + (size_t)row * (NH  * HD) + h * HD;        w = qw; }
    else        { ptr = Kb + (size_t)row * (NKV * HD) + (h - NH) * HD; w = kw; }

    float v = ptr[d];
    float ss = v * v;
#pragma unroll
    for (int o = 16; o > 0; o >>= 1) ss += __shfl_xor_sync(0xffffffffu, ss, o);

    __shared__ float wsum[4];
    if ((d & 31) == 0) wsum[d >> 5] = ss;
    __syncthreads();
    float tot = wsum[0] + wsum[1] + wsum[2] + wsum[3];
    float rn  = rsqrtf(tot * (1.0f / 128.0f) + 1e-6f);
    float vn  = v * rn * w[d];

    __shared__ float sv[128];
    sv[d] = vn;
    __syncthreads();

    const int s = row & (SS - 1);
    const int i = d & 63;
    float c  = g_cos[s * 64 + i];
    float sn = g_sin[s * 64 + i];
    float t1 = sv[i];
    float t2 = sv[i + 64];
    ptr[d] = (d < 64) ? (t1 * c - t2 * sn) : (t1 * sn + t2 * c);
}

// -------------------- Flash attention (fp32, causal, GQA) --------------------
// grid: (S/64 q-tiles, NH heads, B batches), 128 threads (4 warps).
// Each warp owns 16 q rows; lane owns score cols {lane, lane+32} and output dims
// {4*lane .. 4*lane+3}. smem tiles padded to 132 floats/row for conflict-free LDS.
#define FPAD 132
#define FLASH_SMEM (3 * 64 * FPAD * 4)

__global__ __launch_bounds__(128) void flash_kernel(const float* __restrict__ Q,
                                                    const float* __restrict__ K,
                                                    const float* __restrict__ V,
                                                    float* __restrict__ O) {
    extern __shared__ float sm[];
    float* Qs = sm;
    float* Ks = Qs + 64 * FPAD;
    float* Vs = Ks + 64 * FPAD;

    const int qi   = blockIdx.x;
    const int h    = blockIdx.y;
    const int b    = blockIdx.z;
    const int kvh  = h >> 2;             // GQA: q head h uses kv head h/4
    const int tid  = threadIdx.x;
    const int lane = tid & 31;
    const int w    = tid >> 5;
    const int qs   = qi * 64;
    const float scale = 0.08838834764831845f;   // 1/sqrt(128)
    const float NEG = -1e30f;

    // load Q tile (64 rows x 128 cols, padded)
    for (int idx = tid; idx < 64 * 32; idx += 128) {
        int r = idx >> 5, c4 = idx & 31;
        float4 v = *(const float4*)(Q + (size_t)(b * SS + qs + r) * (NH * HD) + h * HD + c4 * 4);
        *(float4*)(Qs + r * FPAD + c4 * 4) = v;
    }

    float m[16], l[16], acc[16][4];
#pragma unroll
    for (int r = 0; r < 16; ++r) {
        m[r] = NEG; l[r] = 0.f;
        acc[r][0] = acc[r][1] = acc[r][2] = acc[r][3] = 0.f;
    }
    __syncthreads();

    for (int kt = 0; kt <= qi; ++kt) {
        const int ks = kt * 64;
        // load K and V tiles
        for (int idx = tid; idx < 64 * 32; idx += 128) {
            int r = idx >> 5, c4 = idx & 31;
            size_t g = (size_t)(b * SS + ks + r) * (NKV * HD) + kvh * HD + c4 * 4;
            *(float4*)(Ks + r * FPAD + c4 * 4) = *(const float4*)(K + g);
            *(float4*)(Vs + r * FPAD + c4 * 4) = *(const float4*)(V + g);
        }
        __syncthreads();

        // ---- scores: s0[r] = Q[row] . K[lane], s1[r] = Q[row] . K[lane+32]
        float s0[16], s1[16];
#pragma unroll
        for (int r = 0; r < 16; ++r) { s0[r] = 0.f; s1[r] = 0.f; }

        const float4* K0 = (const float4*)Ks + (size_t)lane * (FPAD/4);
        const float4* K1 = (const float4*)Ks + (size_t)(lane + 32) * (FPAD/4);
        const float4* Qw = (const float4*)Qs + (size_t)(w * 16) * (FPAD/4);
#pragma unroll 8
        for (int d4 = 0; d4 < 32; ++d4) {
            float4 k0 = K0[d4];
            float4 k1 = K1[d4];
#pragma unroll
            for (int r = 0; r < 16; ++r) {
                float4 q = Qw[r * (FPAD/4) + d4];
                s0[r] += q.x*k0.x + q.y*k0.y + q.z*k0.z + q.w*k0.w;
                s1[r] += q.x*k1.x + q.y*k1.y + q.z*k1.z + q.w*k1.w;
            }
        }

        // ---- online softmax per row; overwrite s0/s1 with probabilities
#pragma unroll
        for (int r = 0; r < 16; ++r) {
            int qg = qs + w * 16 + r;
            float a0 = (ks + lane      <= qg) ? s0[r] * scale : NEG;
            float a1 = (ks + lane + 32 <= qg) ? s1[r] * scale : NEG;
            float mx = fmaxf(a0, a1);
#pragma unroll
            for (int o = 16; o > 0; o >>= 1) mx = fmaxf(mx, __shfl_xor_sync(0xffffffffu, mx, o));
            float mn = fmaxf(m[r], mx);
            float p0 = __expf(a0 - mn);
            float p1 = __expf(a1 - mn);
            float alpha = __expf(m[r] - mn);
            m[r] = mn;
            float ps = p0 + p1;
#pragma unroll
            for (int o = 16; o > 0; o >>= 1) ps += __shfl_xor_sync(0xffffffffu, ps, o);
            l[r] = l[r] * alpha + ps;
            acc[r][0] *= alpha; acc[r][1] *= alpha;
            acc[r][2] *= alpha; acc[r][3] *= alpha;
            s0[r] = p0; s1[r] = p1;
        }

        // ---- O += P @ V  (V rows streamed once per c; P broadcast via shuffle)
        const float4* V4 = (const float4*)Vs;
#pragma unroll
        for (int c = 0; c < 32; ++c) {
            float4 v = V4[c * (FPAD/4) + lane];
#pragma unroll
            for (int r = 0; r < 16; ++r) {
                float p = __shfl_sync(0xffffffffu, s0[r], c);
                acc[r][0] += p * v.x; acc[r][1] += p * v.y;
                acc[r][2] += p * v.z; acc[r][3] += p * v.w;
            }
        }
#pragma unroll
        for (int c = 0; c < 32; ++c) {
            float4 v = V4[(c + 32) * (FPAD/4) + lane];
#pragma unroll
            for (int r = 0; r < 16; ++r) {
                float p = __shfl_sync(0xffffffffu, s1[r], c);
                acc[r][0] += p * v.x; acc[r][1] += p * v.y;
                acc[r][2] += p * v.z; acc[r][3] += p * v.w;
            }
        }
        __syncthreads();
    }

    // epilogue: normalize and write ctx[b, s, h*128 + 4*lane .. +3]
#pragma unroll
    for (int r = 0; r < 16; ++r) {
        float inv = 1.0f / l[r];
        int qg = qs + w * 16 + r;
        float4 o = {acc[r][0] * inv, acc[r][1] * inv, acc[r][2] * inv, acc[r][3] * inv};
        *(float4*)(O + (size_t)(b * SS + qg) * (NH * HD) + h * HD + lane * 4) = o;
    }
}

// -------------------- launch --------------------
extern "C" void kernel_launch(void* const* d_in, const int* in_sizes, int n_in,
                              void* d_out, int out_size) {
    const float* x  = (const float*)d_in[0];
    const float* wq = (const float*)d_in[1];
    const float* wk = (const float*)d_in[2];
    const float* wv = (const float*)d_in[3];
    const float* wo = (const float*)d_in[4];
    const float* qw = (const float*)d_in[5];
    const float* kw = (const float*)d_in[6];
    float* out = (float*)d_out;

    float *qb, *kb, *vb, *ctx;
    cudaGetSymbolAddress((void**)&qb,  g_q);
    cudaGetSymbolAddress((void**)&kb,  g_k);
    cudaGetSymbolAddress((void**)&vb,  g_v);
    cudaGetSymbolAddress((void**)&ctx, g_ctx);

    cudaFuncSetAttribute(flash_kernel, cudaFuncAttributeMaxDynamicSharedMemorySize, FLASH_SMEM);

    // QKV projections
    sgemm128<<<dim3(32, 16), 256>>>(x, wq, qb, MROWS, NH  * HD, HH);
    sgemm128<<<dim3(8,  16), 256>>>(x, wk, kb, MROWS, NKV * HD, HH);
    sgemm128<<<dim3(8,  16), 256>>>(x, wv, vb, MROWS, NKV * HD, HH);

    // RoPE tables + fused RMSNorm/RoPE
    rope_table_kernel<<<64, 1024>>>();
    norm_rope_kernel<<<dim3(MROWS, NH + NKV), 128>>>(qb, kb, qw, kw);

    // causal GQA attention
    flash_kernel<<<dim3(SS / 64, NH, BB), 128, FLASH_SMEM>>>(qb, kb, vb, ctx);

    // output projection
    sgemm128<<<dim3(32, 16), 256>>>(ctx, wo, out, MROWS, NH * HD, HH);
}

// round 5
// speedup vs baseline: 2.3399x; 2.3399x over previous
#include <cuda_runtime.h>
#include <cuda_bf16.h>
#include <math.h>
#include <stdint.h>

// Problem constants
#define BB   2
#define SS   1024
#define HH   4096
#define NH   32
#define NKV  8
#define HD   128
#define MROWS (BB*SS)          // 2048
#define GQA  (NH/NKV)          // 4

// -------------------- scratch (device globals; no allocation) --------------------
__device__ float g_q  [MROWS * NH  * HD];   // 2048 x 4096
__device__ float g_k  [MROWS * NKV * HD];   // 2048 x 1024
__device__ float g_v  [MROWS * NKV * HD];   // 2048 x 1024
__device__ float g_ctx[MROWS * NH  * HD];   // 2048 x 4096
__device__ float g_cos[SS * (HD/2)];        // 1024 x 64
__device__ float g_sin[SS * (HD/2)];

// ==================== TF32 tensor-core GEMM ====================
// C[M,N] = A[M,K] @ B[K,N], row-major. M%128==0, N%128==0, K%32==0.
// 128x128 block tile, BK=32, 256 threads (8 warps), warp tile 64x32,
// mma.sync.m16n8k8.tf32. Double-buffered smem, cvt.rna at staging time.

#define ASTRIDE 36    // 32 + 4 pad: fragment LDS conflict-free
#define BSTRIDE 136   // 128 + 8 pad: fragment LDS conflict-free
#define GEMM_SMEM ((2*(128*ASTRIDE) + 2*(32*BSTRIDE)) * 4)   // 71680 B

__device__ __forceinline__ float to_tf32(float x) {
    float r;
    asm("cvt.rna.tf32.f32 %0, %1;" : "=f"(r) : "f"(x));
    return r;
}

__device__ __forceinline__ void mma_tf32(float& d0, float& d1, float& d2, float& d3,
                                         uint32_t a0, uint32_t a1, uint32_t a2, uint32_t a3,
                                         uint32_t b0, uint32_t b1) {
    asm volatile("mma.sync.aligned.m16n8k8.row.col.f32.tf32.tf32.f32 "
                 "{%0,%1,%2,%3},{%4,%5,%6,%7},{%8,%9},{%0,%1,%2,%3};"
                 : "+f"(d0), "+f"(d1), "+f"(d2), "+f"(d3)
                 : "r"(a0), "r"(a1), "r"(a2), "r"(a3), "r"(b0), "r"(b1));
}

__global__ __launch_bounds__(256) void gemm_tf32(const float* __restrict__ A,
                                                 const float* __restrict__ B,
                                                 float* __restrict__ C,
                                                 int M, int N, int K) {
    extern __shared__ float sm[];
    float* As = sm;                       // [2][128][ASTRIDE]
    float* Bs = sm + 2 * 128 * ASTRIDE;   // [2][32][BSTRIDE]

    const int tid  = threadIdx.x;
    const int lane = tid & 31;
    const int w    = tid >> 5;
    const int g    = lane >> 2;           // group id 0..7
    const int tg   = lane & 3;            // thread-in-group 0..3
    const int wm   = (w & 1) * 64;        // warp m-offset within block
    const int wn   = (w >> 1) * 32;       // warp n-offset within block
    const int bm   = blockIdx.y * 128;
    const int bn   = blockIdx.x * 128;

    float4 regA[4], regB[4];

    const int nk = K / 32;

    // ---- load tile 0
#pragma unroll
    for (int i = 0; i < 4; ++i) {
        int e = tid + i * 256;
        int ar = e >> 3, ac = e & 7;
        regA[i] = *(const float4*)(A + (size_t)(bm + ar) * K + ac * 4);
        int br = e >> 5, bc = e & 31;
        regB[i] = *(const float4*)(B + (size_t)br * N + bn + bc * 4);
    }
#pragma unroll
    for (int i = 0; i < 4; ++i) {
        int e = tid + i * 256;
        int ar = e >> 3, ac = e & 7;
        float* pa = As + ar * ASTRIDE + ac * 4;
        pa[0] = to_tf32(regA[i].x); pa[1] = to_tf32(regA[i].y);
        pa[2] = to_tf32(regA[i].z); pa[3] = to_tf32(regA[i].w);
        int br = e >> 5, bc = e & 31;
        float* pb = Bs + br * BSTRIDE + bc * 4;
        pb[0] = to_tf32(regB[i].x); pb[1] = to_tf32(regB[i].y);
        pb[2] = to_tf32(regB[i].z); pb[3] = to_tf32(regB[i].w);
    }
    __syncthreads();

    float acc[4][4][4];
#pragma unroll
    for (int mi = 0; mi < 4; ++mi)
#pragma unroll
        for (int ni = 0; ni < 4; ++ni)
#pragma unroll
            for (int c = 0; c < 4; ++c) acc[mi][ni][c] = 0.f;

    int buf = 0;
    for (int kt = 0; kt < nk; ++kt) {
        // prefetch next tile to regs
        if (kt + 1 < nk) {
            int koff = (kt + 1) * 32;
#pragma unroll
            for (int i = 0; i < 4; ++i) {
                int e = tid + i * 256;
                int ar = e >> 3, ac = e & 7;
                regA[i] = *(const float4*)(A + (size_t)(bm + ar) * K + koff + ac * 4);
                int br = e >> 5, bc = e & 31;
                regB[i] = *(const float4*)(B + (size_t)(koff + br) * N + bn + bc * 4);
            }
        }

        const float* Ab = As + buf * 128 * ASTRIDE;
        const float* Bb = Bs + buf * 32 * BSTRIDE;

#pragma unroll
        for (int ka = 0; ka < 4; ++ka) {
            const int k0 = ka * 8;
            uint32_t af[4][4], bf[4][2];
#pragma unroll
            for (int mi = 0; mi < 4; ++mi) {
                const float* p = Ab + (size_t)(wm + mi * 16 + g) * ASTRIDE + k0 + tg;
                af[mi][0] = __float_as_uint(p[0]);
                af[mi][1] = __float_as_uint(p[8 * ASTRIDE]);
                af[mi][2] = __float_as_uint(p[4]);
                af[mi][3] = __float_as_uint(p[8 * ASTRIDE + 4]);
            }
#pragma unroll
            for (int ni = 0; ni < 4; ++ni) {
                const float* p = Bb + (size_t)(k0 + tg) * BSTRIDE + wn + ni * 8 + g;
                bf[ni][0] = __float_as_uint(p[0]);
                bf[ni][1] = __float_as_uint(p[4 * BSTRIDE]);
            }
#pragma unroll
            for (int mi = 0; mi < 4; ++mi)
#pragma unroll
                for (int ni = 0; ni < 4; ++ni)
                    mma_tf32(acc[mi][ni][0], acc[mi][ni][1], acc[mi][ni][2], acc[mi][ni][3],
                             af[mi][0], af[mi][1], af[mi][2], af[mi][3],
                             bf[ni][0], bf[ni][1]);
        }

        // stage next tile into the other buffer
        if (kt + 1 < nk) {
            float* Aw = As + (buf ^ 1) * 128 * ASTRIDE;
            float* Bw = Bs + (buf ^ 1) * 32 * BSTRIDE;
#pragma unroll
            for (int i = 0; i < 4; ++i) {
                int e = tid + i * 256;
                int ar = e >> 3, ac = e & 7;
                float* pa = Aw + ar * ASTRIDE + ac * 4;
                pa[0] = to_tf32(regA[i].x); pa[1] = to_tf32(regA[i].y);
                pa[2] = to_tf32(regA[i].z); pa[3] = to_tf32(regA[i].w);
                int br = e >> 5, bc = e & 31;
                float* pb = Bw + br * BSTRIDE + bc * 4;
                pb[0] = to_tf32(regB[i].x); pb[1] = to_tf32(regB[i].y);
                pb[2] = to_tf32(regB[i].z); pb[3] = to_tf32(regB[i].w);
            }
            __syncthreads();
            buf ^= 1;
        }
    }

    // ---- epilogue
#pragma unroll
    for (int mi = 0; mi < 4; ++mi) {
        int r0 = bm + wm + mi * 16 + g;
#pragma unroll
        for (int ni = 0; ni < 4; ++ni) {
            int c0 = bn + wn + ni * 8 + 2 * tg;
            float2 v0 = {acc[mi][ni][0], acc[mi][ni][1]};
            float2 v1 = {acc[mi][ni][2], acc[mi][ni][3]};
            *(float2*)(C + (size_t)r0 * N + c0)       = v0;
            *(float2*)(C + (size_t)(r0 + 8) * N + c0) = v1;
        }
    }
}

// -------------------- RoPE cos/sin table (fp64 precompute -> fp32) --------------------
__global__ void rope_table_kernel() {
    int i = blockIdx.x * blockDim.x + threadIdx.x;      // 0..65535
    if (i >= SS * (HD/2)) return;
    int s = i >> 6;          // position
    int f = i & 63;          // frequency index
    double inv = exp(-(double)f / 64.0 * log(10000.0));
    double a   = (double)s * inv;
    g_cos[i] = (float)cos(a);
    g_sin[i] = (float)sin(a);
}

// -------------------- fused RMSNorm + RoPE (in place on Q and K) --------------------
__global__ __launch_bounds__(128) void norm_rope_kernel(float* __restrict__ Q,
                                                        float* __restrict__ Kb,
                                                        const float* __restrict__ qw,
                                                        const float* __restrict__ kw) {
    const int row = blockIdx.x;       // 0..2047
    const int h   = blockIdx.y;       // 0..39
    const int d   = threadIdx.x;      // 0..127

    float* ptr;
    const float* w;
    if (h < NH) { ptr = Q  + (size_t)row * (NH  * HD) + h * HD;        w = qw; }
    else        { ptr = Kb + (size_t)row * (NKV * HD) + (h - NH) * HD; w = kw; }

    float v = ptr[d];
    float ss = v * v;
#pragma unroll
    for (int o = 16; o > 0; o >>= 1) ss += __shfl_xor_sync(0xffffffffu, ss, o);

    __shared__ float wsum[4];
    if ((d & 31) == 0) wsum[d >> 5] = ss;
    __syncthreads();
    float tot = wsum[0] + wsum[1] + wsum[2] + wsum[3];
    float rn  = rsqrtf(tot * (1.0f / 128.0f) + 1e-6f);
    float vn  = v * rn * w[d];

    __shared__ float sv[128];
    sv[d] = vn;
    __syncthreads();

    const int s = row & (SS - 1);
    const int i = d & 63;
    float c  = g_cos[s * 64 + i];
    float sn = g_sin[s * 64 + i];
    float t1 = sv[i];
    float t2 = sv[i + 64];
    ptr[d] = (d < 64) ? (t1 * c - t2 * sn) : (t1 * sn + t2 * c);
}

// -------------------- Flash attention (fp32, causal, GQA) --------------------
#define FPAD 132
#define FLASH_SMEM (3 * 64 * FPAD * 4)

__global__ __launch_bounds__(128) void flash_kernel(const float* __restrict__ Q,
                                                    const float* __restrict__ K,
                                                    const float* __restrict__ V,
                                                    float* __restrict__ O) {
    extern __shared__ float sm[];
    float* Qs = sm;
    float* Ks = Qs + 64 * FPAD;
    float* Vs = Ks + 64 * FPAD;

    const int qi   = blockIdx.x;
    const int h    = blockIdx.y;
    const int b    = blockIdx.z;
    const int kvh  = h >> 2;
    const int tid  = threadIdx.x;
    const int lane = tid & 31;
    const int w    = tid >> 5;
    const int qs   = qi * 64;
    const float scale = 0.08838834764831845f;   // 1/sqrt(128)
    const float NEG = -1e30f;

    for (int idx = tid; idx < 64 * 32; idx += 128) {
        int r = idx >> 5, c4 = idx & 31;
        float4 v = *(const float4*)(Q + (size_t)(b * SS + qs + r) * (NH * HD) + h * HD + c4 * 4);
        *(float4*)(Qs + r * FPAD + c4 * 4) = v;
    }

    float m[16], l[16], acc[16][4];
#pragma unroll
    for (int r = 0; r < 16; ++r) {
        m[r] = NEG; l[r] = 0.f;
        acc[r][0] = acc[r][1] = acc[r][2] = acc[r][3] = 0.f;
    }
    __syncthreads();

    for (int kt = 0; kt <= qi; ++kt) {
        const int ks = kt * 64;
        for (int idx = tid; idx < 64 * 32; idx += 128) {
            int r = idx >> 5, c4 = idx & 31;
            size_t gg = (size_t)(b * SS + ks + r) * (NKV * HD) + kvh * HD + c4 * 4;
            *(float4*)(Ks + r * FPAD + c4 * 4) = *(const float4*)(K + gg);
            *(float4*)(Vs + r * FPAD + c4 * 4) = *(const float4*)(V + gg);
        }
        __syncthreads();

        float s0[16], s1[16];
#pragma unroll
        for (int r = 0; r < 16; ++r) { s0[r] = 0.f; s1[r] = 0.f; }

        const float4* K0 = (const float4*)Ks + (size_t)lane * (FPAD/4);
        const float4* K1 = (const float4*)Ks + (size_t)(lane + 32) * (FPAD/4);
        const float4* Qw = (const float4*)Qs + (size_t)(w * 16) * (FPAD/4);
#pragma unroll 8
        for (int d4 = 0; d4 < 32; ++d4) {
            float4 k0 = K0[d4];
            float4 k1 = K1[d4];
#pragma unroll
            for (int r = 0; r < 16; ++r) {
                float4 q = Qw[r * (FPAD/4) + d4];
                s0[r] += q.x*k0.x + q.y*k0.y + q.z*k0.z + q.w*k0.w;
                s1[r] += q.x*k1.x + q.y*k1.y + q.z*k1.z + q.w*k1.w;
            }
        }

#pragma unroll
        for (int r = 0; r < 16; ++r) {
            int qg = qs + w * 16 + r;
            float a0 = (ks + lane      <= qg) ? s0[r] * scale : NEG;
            float a1 = (ks + lane + 32 <= qg) ? s1[r] * scale : NEG;
            float mx = fmaxf(a0, a1);
#pragma unroll
            for (int o = 16; o > 0; o >>= 1) mx = fmaxf(mx, __shfl_xor_sync(0xffffffffu, mx, o));
            float mn = fmaxf(m[r], mx);
            float p0 = __expf(a0 - mn);
            float p1 = __expf(a1 - mn);
            float alpha = __expf(m[r] - mn);
            m[r] = mn;
            float ps = p0 + p1;
#pragma unroll
            for (int o = 16; o > 0; o >>= 1) ps += __shfl_xor_sync(0xffffffffu, ps, o);
            l[r] = l[r] * alpha + ps;
            acc[r][0] *= alpha; acc[r][1] *= alpha;
            acc[r][2] *= alpha; acc[r][3] *= alpha;
            s0[r] = p0; s1[r] = p1;
        }

        const float4* V4 = (const float4*)Vs;
#pragma unroll
        for (int c = 0; c < 32; ++c) {
            float4 v = V4[c * (FPAD/4) + lane];
#pragma unroll
            for (int r = 0; r < 16; ++r) {
                float p = __shfl_sync(0xffffffffu, s0[r], c);
                acc[r][0] += p * v.x; acc[r][1] += p * v.y;
                acc[r][2] += p * v.z; acc[r][3] += p * v.w;
            }
        }
#pragma unroll
        for (int c = 0; c < 32; ++c) {
            float4 v = V4[(c + 32) * (FPAD/4) + lane];
#pragma unroll
            for (int r = 0; r < 16; ++r) {
                float p = __shfl_sync(0xffffffffu, s1[r], c);
                acc[r][0] += p * v.x; acc[r][1] += p * v.y;
                acc[r][2] += p * v.z; acc[r][3] += p * v.w;
            }
        }
        __syncthreads();
    }

#pragma unroll
    for (int r = 0; r < 16; ++r) {
        float inv = 1.0f / l[r];
        int qg = qs + w * 16 + r;
        float4 o = {acc[r][0] * inv, acc[r][1] * inv, acc[r][2] * inv, acc[r][3] * inv};
        *(float4*)(O + (size_t)(b * SS + qg) * (NH * HD) + h * HD + lane * 4) = o;
    }
}

// -------------------- launch --------------------
extern "C" void kernel_launch(void* const* d_in, const int* in_sizes, int n_in,
                              void* d_out, int out_size) {
    const float* x  = (const float*)d_in[0];
    const float* wq = (const float*)d_in[1];
    const float* wk = (const float*)d_in[2];
    const float* wv = (const float*)d_in[3];
    const float* wo = (const float*)d_in[4];
    const float* qw = (const float*)d_in[5];
    const float* kw = (const float*)d_in[6];
    float* out = (float*)d_out;

    float *qb, *kb, *vb, *ctx;
    cudaGetSymbolAddress((void**)&qb,  g_q);
    cudaGetSymbolAddress((void**)&kb,  g_k);
    cudaGetSymbolAddress((void**)&vb,  g_v);
    cudaGetSymbolAddress((void**)&ctx, g_ctx);

    cudaFuncSetAttribute(flash_kernel, cudaFuncAttributeMaxDynamicSharedMemorySize, FLASH_SMEM);
    cudaFuncSetAttribute(gemm_tf32,  cudaFuncAttributeMaxDynamicSharedMemorySize, GEMM_SMEM);

    // QKV projections (tf32 tensor cores)
    gemm_tf32<<<dim3(32, 16), 256, GEMM_SMEM>>>(x, wq, qb, MROWS, NH  * HD, HH);
    gemm_tf32<<<dim3(8,  16), 256, GEMM_SMEM>>>(x, wk, kb, MROWS, NKV * HD, HH);
    gemm_tf32<<<dim3(8,  16), 256, GEMM_SMEM>>>(x, wv, vb, MROWS, NKV * HD, HH);

    // RoPE tables + fused RMSNorm/RoPE
    rope_table_kernel<<<64, 1024>>>();
    norm_rope_kernel<<<dim3(MROWS, NH + NKV), 128>>>(qb, kb, qw, kw);

    // causal GQA attention
    flash_kernel<<<dim3(SS / 64, NH, BB), 128, FLASH_SMEM>>>(qb, kb, vb, ctx);

    // output projection
    gemm_tf32<<<dim3(32, 16), 256, GEMM_SMEM>>>(ctx, wo, out, MROWS, NH * HD, HH);
}

// round 6
// speedup vs baseline: 3.3920x; 1.4497x over previous
#include <cuda_runtime.h>
#include <cuda_bf16.h>
#include <math.h>
#include <stdint.h>

// Problem constants
#define BB   2
#define SS   1024
#define HH   4096
#define NH   32
#define NKV  8
#define HD   128
#define MROWS (BB*SS)          // 2048
#define GQA  (NH/NKV)          // 4

// -------------------- scratch (device globals; no allocation) --------------------
__device__ float g_q  [MROWS * NH  * HD];   // 2048 x 4096
__device__ float g_k  [MROWS * NKV * HD];   // 2048 x 1024
__device__ float g_v  [MROWS * NKV * HD];   // 2048 x 1024
__device__ float g_ctx[MROWS * NH  * HD];   // 2048 x 4096
__device__ float g_cos[SS * (HD/2)];        // 1024 x 64
__device__ float g_sin[SS * (HD/2)];

__device__ __forceinline__ float to_tf32(float x) {
    float r;
    asm("cvt.rna.tf32.f32 %0, %1;" : "=f"(r) : "f"(x));
    return r;
}

__device__ __forceinline__ void mma_tf32(float& d0, float& d1, float& d2, float& d3,
                                         uint32_t a0, uint32_t a1, uint32_t a2, uint32_t a3,
                                         uint32_t b0, uint32_t b1) {
    asm volatile("mma.sync.aligned.m16n8k8.row.col.f32.tf32.tf32.f32 "
                 "{%0,%1,%2,%3},{%4,%5,%6,%7},{%8,%9},{%0,%1,%2,%3};"
                 : "+f"(d0), "+f"(d1), "+f"(d2), "+f"(d3)
                 : "r"(a0), "r"(a1), "r"(a2), "r"(a3), "r"(b0), "r"(b1));
}

#define CP_ASYNC16(saddr, gptr) \
    asm volatile("cp.async.cg.shared.global [%0], [%1], 16;" :: "r"(saddr), "l"(gptr))
#define CP_COMMIT() asm volatile("cp.async.commit_group;")
#define CP_WAIT1()  asm volatile("cp.async.wait_group 1;")
#define CP_WAIT0()  asm volatile("cp.async.wait_group 0;")

// ==================== TF32 tensor-core GEMM ====================
// C[M,N] = A[M,K] @ B[K,N], row-major. 128x128 block, BK=32, 256 threads,
// warp tile 64x32, mma.m16n8k8.tf32, double-buffered smem, cvt.rna at staging.

#define ASTRIDE 36
#define BSTRIDE 136
#define GEMM_SMEM ((2*(128*ASTRIDE) + 2*(32*BSTRIDE)) * 4)   // 71680 B

__global__ __launch_bounds__(256) void gemm_tf32(const float* __restrict__ A,
                                                 const float* __restrict__ B,
                                                 float* __restrict__ C,
                                                 int M, int N, int K) {
    extern __shared__ float sm[];
    float* As = sm;                       // [2][128][ASTRIDE]
    float* Bs = sm + 2 * 128 * ASTRIDE;   // [2][32][BSTRIDE]

    const int tid  = threadIdx.x;
    const int lane = tid & 31;
    const int w    = tid >> 5;
    const int g    = lane >> 2;
    const int tg   = lane & 3;
    const int wm   = (w & 1) * 64;
    const int wn   = (w >> 1) * 32;
    const int bm   = blockIdx.y * 128;
    const int bn   = blockIdx.x * 128;

    float4 regA[4], regB[4];
    const int nk = K / 32;

#pragma unroll
    for (int i = 0; i < 4; ++i) {
        int e = tid + i * 256;
        int ar = e >> 3, ac = e & 7;
        regA[i] = *(const float4*)(A + (size_t)(bm + ar) * K + ac * 4);
        int br = e >> 5, bc = e & 31;
        regB[i] = *(const float4*)(B + (size_t)br * N + bn + bc * 4);
    }
#pragma unroll
    for (int i = 0; i < 4; ++i) {
        int e = tid + i * 256;
        int ar = e >> 3, ac = e & 7;
        float* pa = As + ar * ASTRIDE + ac * 4;
        pa[0] = to_tf32(regA[i].x); pa[1] = to_tf32(regA[i].y);
        pa[2] = to_tf32(regA[i].z); pa[3] = to_tf32(regA[i].w);
        int br = e >> 5, bc = e & 31;
        float* pb = Bs + br * BSTRIDE + bc * 4;
        pb[0] = to_tf32(regB[i].x); pb[1] = to_tf32(regB[i].y);
        pb[2] = to_tf32(regB[i].z); pb[3] = to_tf32(regB[i].w);
    }
    __syncthreads();

    float acc[4][4][4];
#pragma unroll
    for (int mi = 0; mi < 4; ++mi)
#pragma unroll
        for (int ni = 0; ni < 4; ++ni)
#pragma unroll
            for (int c = 0; c < 4; ++c) acc[mi][ni][c] = 0.f;

    int buf = 0;
    for (int kt = 0; kt < nk; ++kt) {
        if (kt + 1 < nk) {
            int koff = (kt + 1) * 32;
#pragma unroll
            for (int i = 0; i < 4; ++i) {
                int e = tid + i * 256;
                int ar = e >> 3, ac = e & 7;
                regA[i] = *(const float4*)(A + (size_t)(bm + ar) * K + koff + ac * 4);
                int br = e >> 5, bc = e & 31;
                regB[i] = *(const float4*)(B + (size_t)(koff + br) * N + bn + bc * 4);
            }
        }

        const float* Ab = As + buf * 128 * ASTRIDE;
        const float* Bb = Bs + buf * 32 * BSTRIDE;

#pragma unroll
        for (int ka = 0; ka < 4; ++ka) {
            const int k0 = ka * 8;
            uint32_t af[4][4], bf[4][2];
#pragma unroll
            for (int mi = 0; mi < 4; ++mi) {
                const float* p = Ab + (size_t)(wm + mi * 16 + g) * ASTRIDE + k0 + tg;
                af[mi][0] = __float_as_uint(p[0]);
                af[mi][1] = __float_as_uint(p[8 * ASTRIDE]);
                af[mi][2] = __float_as_uint(p[4]);
                af[mi][3] = __float_as_uint(p[8 * ASTRIDE + 4]);
            }
#pragma unroll
            for (int ni = 0; ni < 4; ++ni) {
                const float* p = Bb + (size_t)(k0 + tg) * BSTRIDE + wn + ni * 8 + g;
                bf[ni][0] = __float_as_uint(p[0]);
                bf[ni][1] = __float_as_uint(p[4 * BSTRIDE]);
            }
#pragma unroll
            for (int mi = 0; mi < 4; ++mi)
#pragma unroll
                for (int ni = 0; ni < 4; ++ni)
                    mma_tf32(acc[mi][ni][0], acc[mi][ni][1], acc[mi][ni][2], acc[mi][ni][3],
                             af[mi][0], af[mi][1], af[mi][2], af[mi][3],
                             bf[ni][0], bf[ni][1]);
        }

        if (kt + 1 < nk) {
            float* Aw = As + (buf ^ 1) * 128 * ASTRIDE;
            float* Bw = Bs + (buf ^ 1) * 32 * BSTRIDE;
#pragma unroll
            for (int i = 0; i < 4; ++i) {
                int e = tid + i * 256;
                int ar = e >> 3, ac = e & 7;
                float* pa = Aw + ar * ASTRIDE + ac * 4;
                pa[0] = to_tf32(regA[i].x); pa[1] = to_tf32(regA[i].y);
                pa[2] = to_tf32(regA[i].z); pa[3] = to_tf32(regA[i].w);
                int br = e >> 5, bc = e & 31;
                float* pb = Bw + br * BSTRIDE + bc * 4;
                pb[0] = to_tf32(regB[i].x); pb[1] = to_tf32(regB[i].y);
                pb[2] = to_tf32(regB[i].z); pb[3] = to_tf32(regB[i].w);
            }
            __syncthreads();
            buf ^= 1;
        }
    }

#pragma unroll
    for (int mi = 0; mi < 4; ++mi) {
        int r0 = bm + wm + mi * 16 + g;
#pragma unroll
        for (int ni = 0; ni < 4; ++ni) {
            int c0 = bn + wn + ni * 8 + 2 * tg;
            float2 v0 = {acc[mi][ni][0], acc[mi][ni][1]};
            float2 v1 = {acc[mi][ni][2], acc[mi][ni][3]};
            *(float2*)(C + (size_t)r0 * N + c0)       = v0;
            *(float2*)(C + (size_t)(r0 + 8) * N + c0) = v1;
        }
    }
}

// -------------------- RoPE cos/sin table --------------------
__global__ void rope_table_kernel() {
    int i = blockIdx.x * blockDim.x + threadIdx.x;
    if (i >= SS * (HD/2)) return;
    int s = i >> 6;
    int f = i & 63;
    double inv = exp(-(double)f / 64.0 * log(10000.0));
    double a   = (double)s * inv;
    g_cos[i] = (float)cos(a);
    g_sin[i] = (float)sin(a);
}

// -------------------- fused RMSNorm + RoPE (writes tf32-rounded) --------------------
__global__ __launch_bounds__(128) void norm_rope_kernel(float* __restrict__ Q,
                                                        float* __restrict__ Kb,
                                                        const float* __restrict__ qw,
                                                        const float* __restrict__ kw) {
    const int row = blockIdx.x;
    const int h   = blockIdx.y;
    const int d   = threadIdx.x;

    float* ptr;
    const float* w;
    if (h < NH) { ptr = Q  + (size_t)row * (NH  * HD) + h * HD;        w = qw; }
    else        { ptr = Kb + (size_t)row * (NKV * HD) + (h - NH) * HD; w = kw; }

    float v = ptr[d];
    float ss = v * v;
#pragma unroll
    for (int o = 16; o > 0; o >>= 1) ss += __shfl_xor_sync(0xffffffffu, ss, o);

    __shared__ float wsum[4];
    if ((d & 31) == 0) wsum[d >> 5] = ss;
    __syncthreads();
    float tot = wsum[0] + wsum[1] + wsum[2] + wsum[3];
    float rn  = rsqrtf(tot * (1.0f / 128.0f) + 1e-6f);
    float vn  = v * rn * w[d];

    __shared__ float sv[128];
    sv[d] = vn;
    __syncthreads();

    const int s = row & (SS - 1);
    const int i = d & 63;
    float c  = g_cos[s * 64 + i];
    float sn = g_sin[s * 64 + i];
    float t1 = sv[i];
    float t2 = sv[i + 64];
    float out = (d < 64) ? (t1 * c - t2 * sn) : (t1 * sn + t2 * c);
    ptr[d] = to_tf32(out);   // pre-rounded for tensor-core flash
}

// -------------------- round V to tf32 in place --------------------
__global__ void v_round_kernel(float* __restrict__ V) {
    int i = blockIdx.x * 1024 + threadIdx.x;
    V[i] = to_tf32(V[i]);
}

// ==================== tensor-core flash attention ====================
// BM=128, BN=64, 8 warps (256 thr). Q resident in smem; K/V double-buffered
// via cp.async. QK^T and PV on mma.m16n8k8.tf32; softmax fp32, log2 domain.
#define QSTR 132   // banks 4g+tg -> conflict-free A/B frags
#define KSTR 132
#define VSTR 136   // banks 8tg+g -> conflict-free PV B frags
#define FL_SMEM ((128*QSTR + 2*64*KSTR + 2*64*VSTR) * 4)   // 204800 B

__global__ __launch_bounds__(256, 1) void flash_mma(const float* __restrict__ Q,
                                                    const float* __restrict__ K,
                                                    const float* __restrict__ V,
                                                    float* __restrict__ O) {
    extern __shared__ float sm[];
    float* Qs = sm;                       // 128 x QSTR
    float* Ks = Qs + 128 * QSTR;          // 2 x 64 x KSTR
    float* Vs = Ks + 2 * 64 * KSTR;       // 2 x 64 x VSTR

    const int qi   = (int)gridDim.x - 1 - (int)blockIdx.x;  // big tiles first
    const int h    = blockIdx.y;
    const int b    = blockIdx.z;
    const int kvh  = h >> 2;
    const int tid  = threadIdx.x;
    const int lane = tid & 31;
    const int w    = tid >> 5;
    const int g    = lane >> 2;
    const int tg   = lane & 3;
    const int qs   = qi * 128;
    const int ntiles = 2 * qi + 2;
    // softmax scale folded with log2(e): exp(x*s) = exp2(x*s*log2e)
    const float scl = 0.08838834764831845f * 1.4426950408889634f;

    const float* Qg = Q + (size_t)(b * SS + qs) * (NH * HD) + h * HD;
    const float* Kg = K + (size_t)(b * SS) * (NKV * HD) + kvh * HD;
    const float* Vg = V + (size_t)(b * SS) * (NKV * HD) + kvh * HD;

    // Q tile: 128 rows x 32 float4 chunks (already tf32-rounded in gmem)
    for (int i = tid; i < 128 * 32; i += 256) {
        int r = i >> 5, c4 = i & 31;
        *(float4*)(Qs + r * QSTR + c4 * 4) =
            *(const float4*)(Qg + (size_t)r * (NH * HD) + c4 * 4);
    }

    // issue K/V tile 0 via cp.async
    for (int i = tid; i < 64 * 32; i += 256) {
        int r = i >> 5, c4 = i & 31;
        const float* kg = Kg + (size_t)r * (NKV * HD) + c4 * 4;
        const float* vg = Vg + (size_t)r * (NKV * HD) + c4 * 4;
        unsigned ka = (unsigned)__cvta_generic_to_shared(Ks + r * KSTR + c4 * 4);
        unsigned va = (unsigned)__cvta_generic_to_shared(Vs + r * VSTR + c4 * 4);
        CP_ASYNC16(ka, kg);
        CP_ASYNC16(va, vg);
    }
    CP_COMMIT();

    float m0 = -1e30f, m1 = -1e30f, l0 = 0.f, l1 = 0.f;
    float acc[16][4];
#pragma unroll
    for (int nt = 0; nt < 16; ++nt)
#pragma unroll
        for (int c = 0; c < 4; ++c) acc[nt][c] = 0.f;

    const int rowg0 = qs + w * 16 + g;
    const int rowg1 = rowg0 + 8;
    const int srcA  = (g << 2) | (tg >> 1);
    const int srcB  = srcA + 2;
    const bool odd  = (tg & 1);

    for (int kt = 0; kt < ntiles; ++kt) {
        __syncthreads();   // prior compute done before buffer overwrite
        if (kt + 1 < ntiles) {
            int bf = (kt + 1) & 1;
            int ks0 = (kt + 1) * 64;
            float* Kw = Ks + bf * 64 * KSTR;
            float* Vw = Vs + bf * 64 * VSTR;
            for (int i = tid; i < 64 * 32; i += 256) {
                int r = i >> 5, c4 = i & 31;
                const float* kg = Kg + (size_t)(ks0 + r) * (NKV * HD) + c4 * 4;
                const float* vg = Vg + (size_t)(ks0 + r) * (NKV * HD) + c4 * 4;
                unsigned ka = (unsigned)__cvta_generic_to_shared(Kw + r * KSTR + c4 * 4);
                unsigned va = (unsigned)__cvta_generic_to_shared(Vw + r * VSTR + c4 * 4);
                CP_ASYNC16(ka, kg);
                CP_ASYNC16(va, vg);
            }
            CP_COMMIT();
            CP_WAIT1();
        } else {
            CP_WAIT0();
        }
        __syncthreads();   // tile kt visible to all

        const float* Kb = Ks + (kt & 1) * 64 * KSTR;
        const float* Vb = Vs + (kt & 1) * 64 * VSTR;

        // ---- S = Q @ K^T  (warp strip: 16 rows x 64 cols)
        float sacc[8][4];
#pragma unroll
        for (int nt = 0; nt < 8; ++nt)
#pragma unroll
            for (int c = 0; c < 4; ++c) sacc[nt][c] = 0.f;

#pragma unroll
        for (int ka = 0; ka < 16; ++ka) {
            const int k0 = ka * 8;
            const float* qp = Qs + (size_t)(w * 16 + g) * QSTR + k0 + tg;
            uint32_t a0 = __float_as_uint(qp[0]);
            uint32_t a1 = __float_as_uint(qp[8 * QSTR]);
            uint32_t a2 = __float_as_uint(qp[4]);
            uint32_t a3 = __float_as_uint(qp[8 * QSTR + 4]);
#pragma unroll
            for (int nt = 0; nt < 8; ++nt) {
                const float* kp = Kb + (size_t)(nt * 8 + g) * KSTR + k0 + tg;
                uint32_t b0 = __float_as_uint(kp[0]);
                uint32_t b1 = __float_as_uint(kp[4]);
                mma_tf32(sacc[nt][0], sacc[nt][1], sacc[nt][2], sacc[nt][3],
                         a0, a1, a2, a3, b0, b1);
            }
        }

        // ---- online softmax (log2 domain), in-place on sacc
        const bool need_mask = (kt >= 2 * qi);
        float mx0 = -1e30f, mx1 = -1e30f;
#pragma unroll
        for (int nt = 0; nt < 8; ++nt) {
            int c0 = kt * 64 + nt * 8 + 2 * tg;
            int c1 = c0 + 1;
            float v0 = sacc[nt][0] * scl, v1 = sacc[nt][1] * scl;
            float v2 = sacc[nt][2] * scl, v3 = sacc[nt][3] * scl;
            if (need_mask) {
                if (c0 > rowg0) v0 = -1e30f;
                if (c1 > rowg0) v1 = -1e30f;
                if (c0 > rowg1) v2 = -1e30f;
                if (c1 > rowg1) v3 = -1e30f;
            }
            sacc[nt][0] = v0; sacc[nt][1] = v1; sacc[nt][2] = v2; sacc[nt][3] = v3;
            mx0 = fmaxf(mx0, fmaxf(v0, v1));
            mx1 = fmaxf(mx1, fmaxf(v2, v3));
        }
        mx0 = fmaxf(mx0, __shfl_xor_sync(0xffffffffu, mx0, 1));
        mx0 = fmaxf(mx0, __shfl_xor_sync(0xffffffffu, mx0, 2));
        mx1 = fmaxf(mx1, __shfl_xor_sync(0xffffffffu, mx1, 1));
        mx1 = fmaxf(mx1, __shfl_xor_sync(0xffffffffu, mx1, 2));

        float mn0 = fmaxf(m0, mx0), mn1 = fmaxf(m1, mx1);
        float al0 = exp2f(m0 - mn0), al1 = exp2f(m1 - mn1);
        m0 = mn0; m1 = mn1;

        float ps0 = 0.f, ps1 = 0.f;
#pragma unroll
        for (int nt = 0; nt < 8; ++nt) {
            float p0 = exp2f(sacc[nt][0] - mn0);
            float p1 = exp2f(sacc[nt][1] - mn0);
            float p2 = exp2f(sacc[nt][2] - mn1);
            float p3 = exp2f(sacc[nt][3] - mn1);
            ps0 += p0 + p1; ps1 += p2 + p3;
            sacc[nt][0] = to_tf32(p0); sacc[nt][1] = to_tf32(p1);
            sacc[nt][2] = to_tf32(p2); sacc[nt][3] = to_tf32(p3);
        }
        ps0 += __shfl_xor_sync(0xffffffffu, ps0, 1);
        ps0 += __shfl_xor_sync(0xffffffffu, ps0, 2);
        ps1 += __shfl_xor_sync(0xffffffffu, ps1, 1);
        ps1 += __shfl_xor_sync(0xffffffffu, ps1, 2);
        l0 = l0 * al0 + ps0;
        l1 = l1 * al1 + ps1;

#pragma unroll
        for (int nt = 0; nt < 16; ++nt) {
            acc[nt][0] *= al0; acc[nt][1] *= al0;
            acc[nt][2] *= al1; acc[nt][3] *= al1;
        }

        // ---- O += P @ V ; A-fragments built from C-fragments via quad shuffles
#pragma unroll
        for (int ka = 0; ka < 8; ++ka) {
            float e0 = __shfl_sync(0xffffffffu, sacc[ka][0], srcA);
            float e1 = __shfl_sync(0xffffffffu, sacc[ka][1], srcA);
            float e2 = __shfl_sync(0xffffffffu, sacc[ka][2], srcA);
            float e3 = __shfl_sync(0xffffffffu, sacc[ka][3], srcA);
            float f0 = __shfl_sync(0xffffffffu, sacc[ka][0], srcB);
            float f1 = __shfl_sync(0xffffffffu, sacc[ka][1], srcB);
            float f2 = __shfl_sync(0xffffffffu, sacc[ka][2], srcB);
            float f3 = __shfl_sync(0xffffffffu, sacc[ka][3], srcB);
            uint32_t pa0 = __float_as_uint(odd ? e1 : e0);
            uint32_t pa1 = __float_as_uint(odd ? e3 : e2);
            uint32_t pa2 = __float_as_uint(odd ? f1 : f0);
            uint32_t pa3 = __float_as_uint(odd ? f3 : f2);
            const int k0 = ka * 8;
#pragma unroll
            for (int nt = 0; nt < 16; ++nt) {
                const float* vp = Vb + (size_t)(k0 + tg) * VSTR + nt * 8 + g;
                uint32_t b0 = __float_as_uint(vp[0]);
                uint32_t b1 = __float_as_uint(vp[4 * VSTR]);
                mma_tf32(acc[nt][0], acc[nt][1], acc[nt][2], acc[nt][3],
                         pa0, pa1, pa2, pa3, b0, b1);
            }
        }
    }

    // ---- epilogue: normalize + store
    float inv0 = 1.0f / l0, inv1 = 1.0f / l1;
    float* Og = O + (size_t)(b * SS + qs + w * 16) * (NH * HD) + h * HD;
#pragma unroll
    for (int nt = 0; nt < 16; ++nt) {
        int col = nt * 8 + 2 * tg;
        float2 o0 = {acc[nt][0] * inv0, acc[nt][1] * inv0};
        float2 o1 = {acc[nt][2] * inv1, acc[nt][3] * inv1};
        *(float2*)(Og + (size_t)g * (NH * HD) + col)       = o0;
        *(float2*)(Og + (size_t)(g + 8) * (NH * HD) + col) = o1;
    }
}

// -------------------- launch --------------------
extern "C" void kernel_launch(void* const* d_in, const int* in_sizes, int n_in,
                              void* d_out, int out_size) {
    const float* x  = (const float*)d_in[0];
    const float* wq = (const float*)d_in[1];
    const float* wk = (const float*)d_in[2];
    const float* wv = (const float*)d_in[3];
    const float* wo = (const float*)d_in[4];
    const float* qw = (const float*)d_in[5];
    const float* kw = (const float*)d_in[6];
    float* out = (float*)d_out;

    float *qb, *kb, *vb, *ctx;
    cudaGetSymbolAddress((void**)&qb,  g_q);
    cudaGetSymbolAddress((void**)&kb,  g_k);
    cudaGetSymbolAddress((void**)&vb,  g_v);
    cudaGetSymbolAddress((void**)&ctx, g_ctx);

    cudaFuncSetAttribute(gemm_tf32, cudaFuncAttributeMaxDynamicSharedMemorySize, GEMM_SMEM);
    cudaFuncSetAttribute(flash_mma, cudaFuncAttributeMaxDynamicSharedMemorySize, FL_SMEM);

    // QKV projections (tf32 tensor cores)
    gemm_tf32<<<dim3(32, 16), 256, GEMM_SMEM>>>(x, wq, qb, MROWS, NH  * HD, HH);
    gemm_tf32<<<dim3(8,  16), 256, GEMM_SMEM>>>(x, wk, kb, MROWS, NKV * HD, HH);
    gemm_tf32<<<dim3(8,  16), 256, GEMM_SMEM>>>(x, wv, vb, MROWS, NKV * HD, HH);

    // RoPE tables + fused RMSNorm/RoPE (tf32-rounded out) + V rounding
    rope_table_kernel<<<64, 1024>>>();
    norm_rope_kernel<<<dim3(MROWS, NH + NKV), 128>>>(qb, kb, qw, kw);
    v_round_kernel<<<(MROWS * NKV * HD) / 1024, 1024>>>(vb);

    // causal GQA attention on tensor cores
    flash_mma<<<dim3(SS / 128, NH, BB), 256, FL_SMEM>>>(qb, kb, vb, ctx);

    // output projection
    gemm_tf32<<<dim3(32, 16), 256, GEMM_SMEM>>>(ctx, wo, out, MROWS, NH * HD, HH);
}